// round 3
// baseline (speedup 1.0000x reference)
#include <cuda_runtime.h>
#include <math.h>

#define NN 100000
#define NE 3200000
#define IN_FEAT 512
#define HID 16
#define NC 7
#define MAXNB 512   // max node-blocks for scan (ceil(100000/256)=391)

// ---------------- scratch (device globals; no allocation allowed) -------------
__device__ int    g_is64;
__device__ int    g_cnt [NN];       // in-degree (edges only, no self-loop)
__device__ int    g_rows[NN];       // CSR row starts
__device__ int    g_cur [NN];       // fill cursors
__device__ int    g_bsum[MAXNB];
__device__ int    g_boff[MAXNB];
__device__ int    g_csr [NE];       // src index per CSR slot
__device__ float  g_dinv[NN];
__device__ float4 g_hn  [NN * 4];   // h1 * dinv (16 f32/node)
__device__ float4 g_acc1[NN * 4];   // gathered sums layer 1 (incl self)
__device__ float4 g_h2n [NN * 2];   // h2 * dinv (7 used + 1 pad)
__device__ float4 g_acc2[NN * 2];   // gathered sums layer 2 (incl self)

// ---------------- dtype detection (int64 vs int32 edge index) -----------------
// If the data is int64 (declared dtype), every odd 32-bit word (high half of
// each nonnegative value < 2^31) is zero. For int32 data those words are live
// random indices — the chance all 32 sampled are zero is ~(1/100000)^32.
__global__ void k_detect(const int* __restrict__ ei) {
    if (threadIdx.x == 0) {
        int nz = 0;
#pragma unroll
        for (int i = 1; i < 64; i += 2) nz |= ei[i];
        g_is64 = (nz == 0) ? 1 : 0;
    }
}

__device__ __forceinline__ int2 load_edge(const void* ei, int e, int E, int is64) {
    if (is64) {
        const long long* p = (const long long*)ei;
        return make_int2((int)p[e], (int)p[(size_t)E + e]);
    } else {
        const int* p = (const int*)ei;
        return make_int2(p[e], p[(size_t)E + e]);
    }
}

// ---------------- degree / CSR build ------------------------------------------
__global__ void k_zero(int n) {
    int i = blockIdx.x * blockDim.x + threadIdx.x;
    if (i < n) g_cnt[i] = 0;
}

__global__ void k_count(const void* __restrict__ ei, int E) {
    int e = blockIdx.x * blockDim.x + threadIdx.x;
    if (e >= E) return;
    int is64 = g_is64;
    int2 sd = load_edge(ei, e, E, is64);
    atomicAdd(&g_cnt[sd.y], 1);
}

__global__ void k_dinv(int n) {
    int i = blockIdx.x * blockDim.x + threadIdx.x;
    if (i < n) g_dinv[i] = rsqrtf((float)(g_cnt[i] + 1));   // +1 self-loop
}

__global__ void k_scan1(int n) {        // per-block sums of counts
    __shared__ int sh[256];
    int i = blockIdx.x * 256 + threadIdx.x;
    sh[threadIdx.x] = (i < n) ? g_cnt[i] : 0;
    __syncthreads();
#pragma unroll
    for (int off = 128; off > 0; off >>= 1) {
        if (threadIdx.x < off) sh[threadIdx.x] += sh[threadIdx.x + off];
        __syncthreads();
    }
    if (threadIdx.x == 0) g_bsum[blockIdx.x] = sh[0];
}

__global__ void k_scan2(int nb) {       // exclusive scan of block sums (1 block)
    __shared__ int sh[MAXNB];
    int t = threadIdx.x;
    int v0 = (t < nb) ? g_bsum[t] : 0;
    sh[t] = v0;
    __syncthreads();
    for (int off = 1; off < MAXNB; off <<= 1) {
        int v = (t >= off) ? sh[t - off] : 0;
        __syncthreads();
        sh[t] += v;
        __syncthreads();
    }
    if (t < nb) g_boff[t] = sh[t] - v0;
}

__global__ void k_scan3(int n) {        // block-local exclusive scan + offset
    __shared__ int sh[256];
    int t = threadIdx.x;
    int i = blockIdx.x * 256 + t;
    int c = (i < n) ? g_cnt[i] : 0;
    sh[t] = c;
    __syncthreads();
#pragma unroll
    for (int off = 1; off < 256; off <<= 1) {
        int v = (t >= off) ? sh[t - off] : 0;
        __syncthreads();
        sh[t] += v;
        __syncthreads();
    }
    if (i < n) {
        int excl = sh[t] - c + g_boff[blockIdx.x];
        g_rows[i] = excl;
        g_cur[i]  = excl;
    }
}

__global__ void k_fill(const void* __restrict__ ei, int E) {
    int e = blockIdx.x * blockDim.x + threadIdx.x;
    if (e >= E) return;
    int is64 = g_is64;
    int2 sd = load_edge(ei, e, E, is64);
    int pos = atomicAdd(&g_cur[sd.y], 1);
    g_csr[pos] = sd.x;
}

// ---------------- layer 1 GEMM: hn = (x @ W1) * dinv --------------------------
// 4 rows per warp; W1^T staged in smem as float4 (reused across the 4 rows).
__global__ void __launch_bounds__(256) k_gemm1(const float* __restrict__ x,
                                               const float* __restrict__ W1,
                                               int n) {
    __shared__ float4 w1t[HID * 128];   // [j][k4]
    for (int i = threadIdx.x; i < HID * 128; i += 256) {
        int j = i >> 7, k4 = i & 127;
        w1t[i] = make_float4(W1[(4 * k4 + 0) * HID + j],
                             W1[(4 * k4 + 1) * HID + j],
                             W1[(4 * k4 + 2) * HID + j],
                             W1[(4 * k4 + 3) * HID + j]);
    }
    __syncthreads();

    int lane = threadIdx.x & 31;
    int warp = (blockIdx.x * blockDim.x + threadIdx.x) >> 5;
    int nw   = (gridDim.x * blockDim.x) >> 5;
    float* hn = (float*)g_hn;

    for (int r0 = warp * 4; r0 < n; r0 += nw * 4) {
        int nr = n - r0 >= 4 ? 4 : n - r0;
        float acc[4][HID];
#pragma unroll
        for (int r = 0; r < 4; r++)
#pragma unroll
            for (int j = 0; j < HID; j++) acc[r][j] = 0.f;

#pragma unroll
        for (int it = 0; it < 4; it++) {
            float4 xv[4];
#pragma unroll
            for (int r = 0; r < 4; r++)
                xv[r] = (r < nr)
                      ? ((const float4*)(x + (size_t)(r0 + r) * IN_FEAT))[it * 32 + lane]
                      : make_float4(0.f, 0.f, 0.f, 0.f);
#pragma unroll
            for (int j = 0; j < HID; j++) {
                float4 w = w1t[j * 128 + it * 32 + lane];
#pragma unroll
                for (int r = 0; r < 4; r++)
                    acc[r][j] += xv[r].x * w.x + xv[r].y * w.y
                               + xv[r].z * w.z + xv[r].w * w.w;
            }
        }
#pragma unroll
        for (int r = 0; r < 4; r++)
#pragma unroll
            for (int j = 0; j < HID; j++)
#pragma unroll
                for (int off = 16; off > 0; off >>= 1)
                    acc[r][j] += __shfl_xor_sync(0xffffffffu, acc[r][j], off);

        if (lane < HID) {
#pragma unroll
            for (int r = 0; r < 4; r++) {
                if (r < nr) {
                    float v = acc[r][0];
#pragma unroll
                    for (int j = 1; j < HID; j++) if (lane == j) v = acc[r][j];
                    int row = r0 + r;
                    hn[(size_t)row * HID + lane] = v * g_dinv[row];
                }
            }
        }
    }
}

// ---------------- layer 1 aggregate (pure gather, no atomics) -----------------
__global__ void k_agg1(int n) {
    int t = blockIdx.x * blockDim.x + threadIdx.x;
    if (t >= n * 4) return;
    int node = t >> 2, c = t & 3;
    int beg = g_rows[node], end = beg + g_cnt[node];
    float4 a = g_hn[(size_t)node * 4 + c];   // self-loop term
    int j = beg;
    for (; j + 2 <= end; j += 2) {
        int s0 = __ldg(&g_csr[j]), s1 = __ldg(&g_csr[j + 1]);
        float4 v0 = g_hn[(size_t)s0 * 4 + c];
        float4 v1 = g_hn[(size_t)s1 * 4 + c];
        a.x += v0.x + v1.x; a.y += v0.y + v1.y;
        a.z += v0.z + v1.z; a.w += v0.w + v1.w;
    }
    if (j < end) {
        int s = __ldg(&g_csr[j]);
        float4 v = g_hn[(size_t)s * 4 + c];
        a.x += v.x; a.y += v.y; a.z += v.z; a.w += v.w;
    }
    g_acc1[t] = a;
}

// ---------------- post1: bias+relu, GEMM2, dinv scale -> h2n ------------------
__global__ void k_post1(const float* __restrict__ b1,
                        const float* __restrict__ W2, int n) {
    __shared__ float w2s[HID * NC];
    __shared__ float b1s[HID];
    if (threadIdx.x < HID * NC) w2s[threadIdx.x] = W2[threadIdx.x];
    if (threadIdx.x < HID)      b1s[threadIdx.x] = b1[threadIdx.x];
    __syncthreads();

    int i = blockIdx.x * blockDim.x + threadIdx.x;
    if (i >= n) return;
    float di = g_dinv[i];
    const float* acc = (const float*)&g_acc1[(size_t)i * 4];

    float h1[HID];
#pragma unroll
    for (int j = 0; j < HID; j++) {
        float v = di * acc[j] + b1s[j];
        h1[j] = v > 0.f ? v : 0.f;
    }
    float o[NC];
#pragma unroll
    for (int c = 0; c < NC; c++) o[c] = 0.f;
#pragma unroll
    for (int k = 0; k < HID; k++) {
        float hv = h1[k];
#pragma unroll
        for (int c = 0; c < NC; c++) o[c] += hv * w2s[k * NC + c];
    }
    float* out = (float*)&g_h2n[(size_t)i * 2];
#pragma unroll
    for (int c = 0; c < NC; c++) out[c] = o[c] * di;
    out[7] = 0.f;
}

// ---------------- layer 2 aggregate -------------------------------------------
__global__ void k_agg2(int n) {
    int t = blockIdx.x * blockDim.x + threadIdx.x;
    if (t >= n * 2) return;
    int node = t >> 1, c = t & 1;
    int beg = g_rows[node], end = beg + g_cnt[node];
    float4 a = g_h2n[(size_t)node * 2 + c];  // self-loop term
    int j = beg;
    for (; j + 2 <= end; j += 2) {
        int s0 = __ldg(&g_csr[j]), s1 = __ldg(&g_csr[j + 1]);
        float4 v0 = g_h2n[(size_t)s0 * 2 + c];
        float4 v1 = g_h2n[(size_t)s1 * 2 + c];
        a.x += v0.x + v1.x; a.y += v0.y + v1.y;
        a.z += v0.z + v1.z; a.w += v0.w + v1.w;
    }
    if (j < end) {
        int s = __ldg(&g_csr[j]);
        float4 v = g_h2n[(size_t)s * 2 + c];
        a.x += v.x; a.y += v.y; a.z += v.z; a.w += v.w;
    }
    g_acc2[t] = a;
}

// ---------------- post2: logits + log_softmax ---------------------------------
__global__ void k_post2(const float* __restrict__ b2, float* __restrict__ outp, int n) {
    __shared__ float b2s[NC];
    if (threadIdx.x < NC) b2s[threadIdx.x] = b2[threadIdx.x];
    __syncthreads();

    int i = blockIdx.x * blockDim.x + threadIdx.x;
    if (i >= n) return;
    float di = g_dinv[i];
    const float* acc = (const float*)&g_acc2[(size_t)i * 2];

    float lg[NC];
    float m = -1e30f;
#pragma unroll
    for (int c = 0; c < NC; c++) {
        lg[c] = di * acc[c] + b2s[c];
        m = fmaxf(m, lg[c]);
    }
    float s = 0.f;
#pragma unroll
    for (int c = 0; c < NC; c++) s += expf(lg[c] - m);
    float ls = logf(s) + m;
#pragma unroll
    for (int c = 0; c < NC; c++) outp[(size_t)i * NC + c] = lg[c] - ls;
}

// ---------------- launch ------------------------------------------------------
extern "C" void kernel_launch(void* const* d_in, const int* in_sizes, int n_in,
                              void* d_out, int out_size) {
    const float* x  = (const float*)d_in[0];
    const void*  ei = d_in[1];
    const float* W1 = (const float*)d_in[2];
    const float* b1 = (const float*)d_in[3];
    const float* W2 = (const float*)d_in[4];
    const float* b2 = (const float*)d_in[5];
    float*       out = (float*)d_out;

    int n = in_sizes[0] / IN_FEAT;   // 100000
    int E = in_sizes[1] / 2;         // 3200000

    const int T = 256;
    int nb = (n + T - 1) / T;        // 391
    int eb = (E + T - 1) / T;

    k_detect<<<1, 32>>>((const int*)ei);
    k_zero  <<<nb, T>>>(n);
    k_count <<<eb, T>>>(ei, E);
    k_dinv  <<<nb, T>>>(n);
    k_scan1 <<<nb, T>>>(n);
    k_scan2 <<<1, MAXNB>>>(nb);
    k_scan3 <<<nb, T>>>(n);
    k_fill  <<<eb, T>>>(ei, E);
    k_gemm1 <<<592, T>>>(x, W1, n);
    k_agg1  <<<(n * 4 + T - 1) / T, T>>>(n);
    k_post1 <<<nb, T>>>(b1, W2, n);
    k_agg2  <<<(n * 2 + T - 1) / T, T>>>(n);
    k_post2 <<<nb, T>>>(b2, out, n);
}